// round 14
// baseline (speedup 1.0000x reference)
#include <cuda_runtime.h>
#include <cuda_bf16.h>

#define NCTA 64
#define NTHR 512
#define TSTEPS 512

typedef unsigned long long u64;
typedef unsigned int u32;

// ---------------- persistent device state ----------------
__device__ float g_hT[1024 * 64];                    // fp32 h for head
__device__ __align__(16) uint4 g_Phi[7][8192];       // fragment-order A planes (bf16-hi)
__device__ __align__(16) uint4 g_Plo[7][8192];       // fragment-order A planes (bf16-lo)
// plane ids: 0=emb 1=s0 2=s1 3=s2 4=s3 5=s5 6=h
__device__ __align__(16) u64 g_Whi[5242880];         // pair-interleaved B weights (bf16-hi)
__device__ __align__(16) u64 g_Wlo[5242880];         // bf16-lo
__device__ unsigned g_flags[NCTA];                   // per-CTA barrier flags (monotonic)

// uint4 offsets into weight arrays: L0 at 0 (128 pairs x 128 kt), node i after it
#define W4OFF(i) (524288u + (u32)(i) * 262144u)

// ---------------- helpers ----------------
__device__ __forceinline__ float sigm(float x) { return 1.f / (1.f + expf(-x)); }
__device__ __forceinline__ float actf(int code, float x) {
    switch (code) {
        case 0:  return tanhf(x);
        case 1:  return fmaxf(x, 0.f);
        case 2:  return sigm(x);
        default: return x;
    }
}
__device__ __forceinline__ float ldcg_f(const float* p) {
    float v; asm volatile("ld.global.cg.f32 %0, [%1];" : "=f"(v) : "l"(p)); return v;
}
__device__ __forceinline__ void cp_async16(void* smem_dst, const void* gsrc) {
    unsigned s = (unsigned)__cvta_generic_to_shared(smem_dst);
    asm volatile("cp.async.cg.shared.global [%0], [%1], 16;" :: "r"(s), "l"(gsrc));
}
#define CP_COMMIT() asm volatile("cp.async.commit_group;")

__device__ __forceinline__ void mma_bf16(float* d, u32 a0, u32 a1, u32 a2, u32 a3,
                                         u32 b0, u32 b1) {
    asm("mma.sync.aligned.m16n8k16.row.col.f32.bf16.bf16.f32 "
        "{%0,%1,%2,%3},{%4,%5,%6,%7},{%8,%9},{%0,%1,%2,%3};"
        : "+f"(d[0]), "+f"(d[1]), "+f"(d[2]), "+f"(d[3])
        : "r"(a0), "r"(a1), "r"(a2), "r"(a3), "r"(b0), "r"(b1));
}

__device__ __forceinline__ u64 pack4(__nv_bfloat16 a, __nv_bfloat16 b,
                                     __nv_bfloat16 c, __nv_bfloat16 d) {
    return (u64)__bfloat16_as_ushort(a) | ((u64)__bfloat16_as_ushort(b) << 16)
         | ((u64)__bfloat16_as_ushort(c) << 32) | ((u64)__bfloat16_as_ushort(d) << 48);
}
__device__ __forceinline__ void packhl(float v0, float v1, float v2, float v3,
                                       u64& hi, u64& lo) {
    __nv_bfloat16 h0 = __float2bfloat16_rn(v0), h1 = __float2bfloat16_rn(v1),
                  h2 = __float2bfloat16_rn(v2), h3 = __float2bfloat16_rn(v3);
    __nv_bfloat16 l0 = __float2bfloat16_rn(v0 - __bfloat162float(h0)),
                  l1 = __float2bfloat16_rn(v1 - __bfloat162float(h1)),
                  l2 = __float2bfloat16_rn(v2 - __bfloat162float(h2)),
                  l3 = __float2bfloat16_rn(v3 - __bfloat162float(h3));
    hi = pack4(h0, h1, h2, h3);
    lo = pack4(l0, l1, l2, l3);
}

// Flag-array grid barrier (64 CTAs).
__device__ __forceinline__ void grid_sync(unsigned e) {
    __threadfence();
    __syncthreads();
    if (threadIdx.x == 0)
        *((volatile unsigned*)&g_flags[blockIdx.x]) = e;
    if (threadIdx.x < NCTA) {
        while (*((volatile unsigned*)&g_flags[threadIdx.x]) < e) { }
    }
    __syncthreads();
}

// Write this CTA's 16 state cols (scratch[col*65+row]) into an A plane. tt in [0,256).
__device__ __forceinline__ void swz_scr(const float* sc, u64* dh, u64* dl, int cta, int tt) {
    int mt = tt >> 6;
    int rest = tt & 63;
    int lane = rest >> 1;
    int half = rest & 1;
    int g = lane >> 2, c = lane & 3;
    int jA = half * 8 + 2 * c;                 // col within CTA's 16
    int mA = mt * 16 + g, mB = mA + 8;
    float v00 = sc[jA * 65 + mA], v01 = sc[(jA + 1) * 65 + mA];
    float v10 = sc[jA * 65 + mB], v11 = sc[(jA + 1) * 65 + mB];
    u64 hi, lo; packhl(v00, v01, v10, v11, hi, lo);
    int idx = (((cta * 4 + mt) * 32 + lane) << 1) + half;
    dh[idx] = hi; dl[idx] = lo;
}

// Gather embedding rows directly into the fragment-order emb plane. tt in [0,256).
__device__ __forceinline__ void swz_emb(const float* __restrict__ emb, const int* stok,
                                        u64* dh, u64* dl, int cta, int tt) {
    int mt = tt >> 6;
    int rest = tt & 63;
    int lane = rest >> 1;
    int half = rest & 1;
    int g = lane >> 2, c = lane & 3;
    int col = cta * 16 + half * 8 + 2 * c;
    int mA = mt * 16 + g, mB = mA + 8;
    size_t tA = (size_t)stok[mA] * 1024, tB = (size_t)stok[mB] * 1024;
    float v00 = __ldg(emb + tA + col), v01 = __ldg(emb + tA + col + 1);
    float v10 = __ldg(emb + tB + col), v11 = __ldg(emb + tB + col + 1);
    u64 hi, lo; packhl(v00, v01, v10, v11, hi, lo);
    int idx = (((cta * 4 + mt) * 32 + lane) << 1) + half;
    dh[idx] = hi; dl[idx] = lo;
}

// One GEMM pass: out(16 cols x 64 rows) = gated(pred) with pre-act = x @ W.
// A staged through 3-slot smem ring (32KB chunks = 8 kt); B via pair-interleaved LDG.128.
// 16 warps = 4 mt x 2 nt x 2 kh (kh splits each chunk).
__device__ __forceinline__ void gemm_pass(
    const uint4* __restrict__ PAh, const uint4* __restrict__ PAl,
    const uint4* __restrict__ PBh, const uint4* __restrict__ PBl,
    int nchunks, int switchc,
    const uint4* __restrict__ w4h, const uint4* __restrict__ w4l, int nkt,
    int act, float sp0, float sp1, float* o2,
    u64* ozh, u64* ozl,
    uint4* dynsm, float* scratch, int cta)
{
    const int tid = threadIdx.x;
    const int lane = tid & 31, warp = tid >> 5;
    const int mt = warp & 3, nt = (warp >> 2) & 1, kh = warp >> 3;
    const u32 p = nt ? (u32)(64 + cta) : (u32)cta;            // n8-pair index
    const u32 pb = p * (u32)nkt * 32u + (u32)lane;

    float acc0[4] = {0.f, 0.f, 0.f, 0.f};                     // sub0 (first n8 of pair)
    float acc1[4] = {0.f, 0.f, 0.f, 0.f};                     // sub1

    // prologue: stage chunks 0,1
    #pragma unroll
    for (int c0 = 0; c0 < 2; c0++) {
        const uint4* sh = (c0 < switchc) ? PAh + c0 * 1024 : PBh + (c0 - switchc) * 1024;
        const uint4* sl = (c0 < switchc) ? PAl + c0 * 1024 : PBl + (c0 - switchc) * 1024;
        uint4* slot = dynsm + c0 * 2048;
        cp_async16(slot + tid, sh + tid);
        cp_async16(slot + 512 + tid, sh + 512 + tid);
        cp_async16(slot + 1024 + tid, sl + tid);
        cp_async16(slot + 1536 + tid, sl + 512 + tid);
        CP_COMMIT();
    }

    for (int c = 0; c < nchunks; c++) {
        if (c + 2 < nchunks) {
            asm volatile("cp.async.wait_group 1;");
            __syncthreads();
            int cn = c + 2;
            const uint4* sh = (cn < switchc) ? PAh + cn * 1024 : PBh + (cn - switchc) * 1024;
            const uint4* sl = (cn < switchc) ? PAl + cn * 1024 : PBl + (cn - switchc) * 1024;
            uint4* slot = dynsm + (cn % 3) * 2048;
            cp_async16(slot + tid, sh + tid);
            cp_async16(slot + 512 + tid, sh + 512 + tid);
            cp_async16(slot + 1024 + tid, sl + tid);
            cp_async16(slot + 1536 + tid, sl + 512 + tid);
            CP_COMMIT();
        } else if (c + 2 == nchunks) {
            asm volatile("cp.async.wait_group 1;");
            __syncthreads();
        } else {
            asm volatile("cp.async.wait_group 0;");
            __syncthreads();
        }

        const uint4* sA = dynsm + (c % 3) * 2048;
        const u32 kbase = (u32)(c * 8 + kh * 4);
        #pragma unroll
        for (int i = 0; i < 4; i++) {
            const int kf = kh * 4 + i;
            uint4 ah = sA[(kf * 4 + mt) * 32 + lane];
            uint4 al = sA[1024 + (kf * 4 + mt) * 32 + lane];
            uint4 bh = __ldg(w4h + pb + (kbase + (u32)i) * 32u);
            uint4 bl = __ldg(w4l + pb + (kbase + (u32)i) * 32u);
            mma_bf16(acc0, ah.x, ah.y, ah.z, ah.w, bh.x, bh.y);
            mma_bf16(acc0, ah.x, ah.y, ah.z, ah.w, bl.x, bl.y);
            mma_bf16(acc0, al.x, al.y, al.z, al.w, bh.x, bh.y);
            mma_bf16(acc1, ah.x, ah.y, ah.z, ah.w, bh.z, bh.w);
            mma_bf16(acc1, ah.x, ah.y, ah.z, ah.w, bl.z, bl.w);
            mma_bf16(acc1, al.x, al.y, al.z, al.w, bh.z, bh.w);
        }
    }

    // epilogue: cross-kh reduction in smem (aliases staging ring; all chunks consumed)
    __syncthreads();
    float* bufA = (float*)dynsm;              // [32][65] per kh
    float* bufB = bufA + 32 * 65;
    float* mybuf = kh ? bufB : bufA;
    {
        int g = lane >> 2, cc = lane & 3;
        int m0 = mt * 16 + g;
        int nl0 = nt * 16 + 2 * cc;           // sub0 cols
        mybuf[nl0 * 65 + m0]           = acc0[0];
        mybuf[(nl0 + 1) * 65 + m0]     = acc0[1];
        mybuf[nl0 * 65 + m0 + 8]       = acc0[2];
        mybuf[(nl0 + 1) * 65 + m0 + 8] = acc0[3];
        int nl1 = nl0 + 8;                    // sub1 cols
        mybuf[nl1 * 65 + m0]           = acc1[0];
        mybuf[(nl1 + 1) * 65 + m0]     = acc1[1];
        mybuf[nl1 * 65 + m0 + 8]       = acc1[2];
        mybuf[(nl1 + 1) * 65 + m0 + 8] = acc1[3];
    }
    __syncthreads();
    {
        int c16 = tid & 15, r0 = tid >> 4, r1 = r0 + 32;
        float cp0 = bufA[c16 * 65 + r0] + bufB[c16 * 65 + r0];
        float hp0 = bufA[(16 + c16) * 65 + r0] + bufB[(16 + c16) * 65 + r0];
        float cp1 = bufA[c16 * 65 + r1] + bufB[c16 * 65 + r1];
        float hp1 = bufA[(16 + c16) * 65 + r1] + bufB[(16 + c16) * 65 + r1];
        float v0 = sp0 + sigm(cp0) * (actf(act, hp0) - sp0);
        float v1 = sp1 + sigm(cp1) * (actf(act, hp1) - sp1);
        o2[0] = v0; o2[1] = v1;
        if (ozh) {
            scratch[c16 * 65 + r0] = v0;
            scratch[c16 * 65 + r1] = v1;
        }
    }
    if (ozh) {
        __syncthreads();
        if (tid < 256) swz_scr(scratch, ozh, ozl, cta, tid);
    }
    __syncthreads();   // protect bufs/scratch before next pass stages over them
}

// ---------------- the persistent kernel ----------------
__global__ __launch_bounds__(NTHR, 1) void darts_mma64_kernel(
    const int* __restrict__ X, const float* __restrict__ hidden,
    const float* __restrict__ emb, const float* __restrict__ W0,
    const float* __restrict__ Ws, const float* __restrict__ Wout,
    const float* __restrict__ bout, float* __restrict__ out, int out_size)
{
    extern __shared__ uint4 dynsm[];          // 96 KB: 3 x 2048-uint4 staging slots
    __shared__ float scratch[16 * 65];
    __shared__ int stok[64];

    const int cta = blockIdx.x;
    const int tid = threadIdx.x;
    const int c16 = tid & 15, r0 = tid >> 4, r1 = r0 + 32;
    const int col = cta * 16 + c16;
    unsigned epoch = *((volatile unsigned*)&g_flags[cta]);

    // Phase 1: weights fp32 -> pair-interleaved fragment uint4s (hi/lo).
    for (u32 q4 = (u32)(cta * NTHR + tid); q4 < 2621440u; q4 += (u32)(NCTA * NTHR)) {
        const float* src; u32 p, kt, lane;
        if (q4 < 524288u) {
            src = W0; p = q4 >> 12; kt = (q4 >> 5) & 127u; lane = q4 & 31u;
        } else {
            u32 r = q4 - 524288u;
            src = Ws + (size_t)(r >> 18) * 2097152u;
            r &= 262143u; p = r >> 11; kt = (r >> 5) & 63u; lane = r & 31u;
        }
        u32 g = lane >> 2, c = lane & 3;
        u32 k0 = kt * 16 + 2 * c;
        #pragma unroll
        for (u32 sub = 0; sub < 2; sub++) {
            u32 n = (2 * p + sub) * 8 + g;
            float v0 = __ldg(src + (size_t)k0 * 2048 + n);
            float v1 = __ldg(src + (size_t)(k0 + 1) * 2048 + n);
            float v2 = __ldg(src + (size_t)(k0 + 8) * 2048 + n);
            float v3 = __ldg(src + (size_t)(k0 + 9) * 2048 + n);
            u64 hi, lo; packhl(v0, v1, v2, v3, hi, lo);
            g_Whi[(size_t)q4 * 2 + sub] = hi;
            g_Wlo[(size_t)q4 * 2 + sub] = lo;
        }
    }

    // Phase 2: init h plane + emb plane for t=0.
    float h0 = __ldg(&hidden[r0 * 1024 + col]);
    float h1 = __ldg(&hidden[r1 * 1024 + col]);
    scratch[c16 * 65 + r0] = h0;
    scratch[c16 * 65 + r1] = h1;
    if (tid < 64) stok[tid] = __ldg(&X[tid]);
    __syncthreads();
    if (tid < 256) swz_scr(scratch, (u64*)g_Phi[6], (u64*)g_Plo[6], cta, tid);
    else swz_emb(emb, stok, (u64*)g_Phi[0], (u64*)g_Plo[0], cta, tid - 256);
    grid_sync(++epoch);

    const uint4* Wh4 = (const uint4*)g_Whi;
    const uint4* Wl4 = (const uint4*)g_Wlo;
    float s0v[2], s1v[2], s2v[2], s3v[2], s4v[2], s5v[2], s6v[2], s7v[2], s8v[2];

    for (int t = 0; t < TSTEPS; t++) {
        // L0: s0 = gate([emb;h] @ W0), base h, tanh. 16 chunks (emb plane then h plane).
        gemm_pass(g_Phi[0], g_Plo[0], g_Phi[6], g_Plo[6], 16, 8,
                  Wh4, Wl4, 128, 0, h0, h1, s0v,
                  (u64*)g_Phi[1], (u64*)g_Plo[1], dynsm, scratch, cta);
        grid_sync(++epoch);

        // L1: s1 = node0(s0), sigmoid
        gemm_pass(g_Phi[1], g_Plo[1], g_Phi[1], g_Plo[1], 8, 8,
                  Wh4 + W4OFF(0), Wl4 + W4OFF(0), 64, 2, s0v[0], s0v[1], s1v,
                  (u64*)g_Phi[2], (u64*)g_Plo[2], dynsm, scratch, cta);
        grid_sync(++epoch);

        // L2: s2 = node1(s1) relu, s3 = node2(s1) relu, s4 = node3(s1) id
        gemm_pass(g_Phi[2], g_Plo[2], g_Phi[2], g_Plo[2], 8, 8,
                  Wh4 + W4OFF(1), Wl4 + W4OFF(1), 64, 1, s1v[0], s1v[1], s2v,
                  (u64*)g_Phi[3], (u64*)g_Plo[3], dynsm, scratch, cta);
        gemm_pass(g_Phi[2], g_Plo[2], g_Phi[2], g_Plo[2], 8, 8,
                  Wh4 + W4OFF(2), Wl4 + W4OFF(2), 64, 1, s1v[0], s1v[1], s3v,
                  (u64*)g_Phi[4], (u64*)g_Plo[4], dynsm, scratch, cta);
        gemm_pass(g_Phi[2], g_Plo[2], g_Phi[2], g_Plo[2], 8, 8,
                  Wh4 + W4OFF(3), Wl4 + W4OFF(3), 64, 3, s1v[0], s1v[1], s4v,
                  (u64*)0, (u64*)0, dynsm, scratch, cta);
        grid_sync(++epoch);

        // L3: s5 = node4(s2) tanh; s7 = node6(s3) tanh (both inputs ready)
        gemm_pass(g_Phi[3], g_Plo[3], g_Phi[3], g_Plo[3], 8, 8,
                  Wh4 + W4OFF(4), Wl4 + W4OFF(4), 64, 0, s2v[0], s2v[1], s5v,
                  (u64*)g_Phi[5], (u64*)g_Plo[5], dynsm, scratch, cta);
        gemm_pass(g_Phi[4], g_Plo[4], g_Phi[4], g_Plo[4], 8, 8,
                  Wh4 + W4OFF(6), Wl4 + W4OFF(6), 64, 0, s3v[0], s3v[1], s7v,
                  (u64*)0, (u64*)0, dynsm, scratch, cta);
        grid_sync(++epoch);

        // L4: s6 = node5(s5) sigmoid, s8 = node7(s5) relu
        gemm_pass(g_Phi[5], g_Plo[5], g_Phi[5], g_Plo[5], 8, 8,
                  Wh4 + W4OFF(5), Wl4 + W4OFF(5), 64, 2, s5v[0], s5v[1], s6v,
                  (u64*)0, (u64*)0, dynsm, scratch, cta);
        gemm_pass(g_Phi[5], g_Plo[5], g_Phi[5], g_Plo[5], 8, 8,
                  Wh4 + W4OFF(7), Wl4 + W4OFF(7), 64, 1, s5v[0], s5v[1], s8v,
                  (u64*)0, (u64*)0, dynsm, scratch, cta);

        // combine: h = mean(s1..s8); write h plane + next emb plane
        h0 = 0.125f * (s1v[0] + s2v[0] + s3v[0] + s4v[0] + s5v[0] + s6v[0] + s7v[0] + s8v[0]);
        h1 = 0.125f * (s1v[1] + s2v[1] + s3v[1] + s4v[1] + s5v[1] + s6v[1] + s7v[1] + s8v[1]);
        scratch[c16 * 65 + r0] = h0;
        scratch[c16 * 65 + r1] = h1;
        if (tid < 64 && t + 1 < TSTEPS) stok[tid] = __ldg(&X[(t + 1) * 64 + tid]);
        __syncthreads();
        if (tid < 256) swz_scr(scratch, (u64*)g_Phi[6], (u64*)g_Plo[6], cta, tid);
        else if (t + 1 < TSTEPS)
            swz_emb(emb, stok, (u64*)g_Phi[0], (u64*)g_Plo[0], cta, tid - 256);
        grid_sync(++epoch);
    }

    // publish final h for the head
    g_hT[col * 64 + r0] = h0;
    g_hT[col * 64 + r1] = h1;
    grid_sync(++epoch);

    // head: a_hat = h @ W_out + b_out; probs = softmax over 4 (lane-aligned groups)
    if (cta == 0 && tid < 256) {
        int b = tid >> 2, oo = tid & 3;
        float acc = 0.f;
        for (int k = 0; k < 1024; k++)
            acc += ldcg_f(&g_hT[k * 64 + b]) * __ldg(&Wout[k * 4 + oo]);
        acc += __ldg(&bout[oo]);
        float mx = acc;
        mx = fmaxf(mx, __shfl_xor_sync(0xFFFFFFFFu, mx, 1));
        mx = fmaxf(mx, __shfl_xor_sync(0xFFFFFFFFu, mx, 2));
        float e = expf(acc - mx);
        float ssum = e;
        ssum += __shfl_xor_sync(0xFFFFFFFFu, ssum, 1);
        ssum += __shfl_xor_sync(0xFFFFFFFFu, ssum, 2);
        out[b * 4 + oo] = acc;
        if (out_size >= 512) out[256 + b * 4 + oo] = e / ssum;
    }
}

extern "C" void kernel_launch(void* const* d_in, const int* in_sizes, int n_in,
                              void* d_out, int out_size) {
    const int*   X      = (const int*)d_in[0];
    const float* hidden = (const float*)d_in[1];
    const float* emb    = (const float*)d_in[2];
    const float* W0     = (const float*)d_in[3];
    const float* Ws     = (const float*)d_in[4];
    const float* W_out  = (const float*)d_in[5];
    const float* b_out  = (const float*)d_in[6];
    (void)in_sizes; (void)n_in;

    cudaFuncSetAttribute(darts_mma64_kernel,
                         cudaFuncAttributeMaxDynamicSharedMemorySize, 98304);
    darts_mma64_kernel<<<NCTA, NTHR, 98304>>>(X, hidden, emb, W0, Ws, W_out, b_out,
                                              (float*)d_out, out_size);
}